// round 1
// baseline (speedup 1.0000x reference)
#include <cuda_runtime.h>

#define TM   128   // m rows per block (= threads)
#define TN   64    // n-tile depth
#define BDIM 16    // batch
#define CO   64    // cout (without density)
#define RDIM 128   // output channels

// Dynamic SMEM layout (bytes):
//  mainloop:  [0,256)   cs[TN]            [256, 256+16384)  co_s[TN][64]
//  epilogue:  [0,34816) v_s[128][68]      [34816,69632) W_s[128][68]   [69632,70144) b_s[128]
#define SMEM_BYTES 70144

// exp2(y) for y in [-120, 0], pure FMA/ALU (no MUFU): ~3e-6 rel err
__device__ __forceinline__ float fast_exp2(float y) {
    y = fmaxf(y, -120.0f);
    float t = y + 12582912.0f;                    // round-to-nearest int via magic add
    int   ni = __float_as_int(t) - 0x4B400000;    // integer part n
    float n  = t - 12582912.0f;
    float f  = y - n;                             // f in [-0.5, 0.5]
    float p  = 1.3333558146e-3f;
    p = fmaf(p, f, 9.6181291076e-3f);
    p = fmaf(p, f, 5.5504108664e-2f);
    p = fmaf(p, f, 2.4022650696e-1f);
    p = fmaf(p, f, 6.9314718056e-1f);
    p = fmaf(p, f, 1.0f);
    return __int_as_float(__float_as_int(p) + (ni << 23));
}

__global__ void __launch_bounds__(TM, 3)
convdeepset_kernel(const float* __restrict__ ci,   // (N,B,1)
                   const float* __restrict__ co,   // (N,B,64)
                   const float* __restrict__ ti,   // (M,B,1)
                   const float* __restrict__ ls,   // (1,)
                   const float* __restrict__ W,    // (128,65)
                   const float* __restrict__ bias, // (128,)
                   float* __restrict__ out,        // (M,B,128)
                   int N, int M)
{
    extern __shared__ float smem[];
    float* cs   = smem;        // TN floats
    float* co_s = smem + 64;   // TN*64 floats, 16B aligned

    const int tid = threadIdx.x;
    const int bb  = blockIdx.y;
    const int m   = blockIdx.x * TM + tid;

    const float tval = ti[m * BDIM + bb];
    const float lsv  = ls[0];
    const float cexp = -0.72134752044448170f / (lsv * lsv);  // -0.5*log2(e)/ls^2

    float  acc0 = 0.0f;
    float4 accv[16];
    #pragma unroll
    for (int q = 0; q < 16; ++q) accv[q] = make_float4(0.f, 0.f, 0.f, 0.f);

    for (int n0 = 0; n0 < N; n0 += TN) {
        __syncthreads();
        if (tid < TN) cs[tid] = ci[(n0 + tid) * BDIM + bb];
        // stage co tile: TN rows x 64 floats, float4-coalesced
        #pragma unroll
        for (int i = tid; i < TN * 16; i += TM) {
            int j  = i >> 4;
            int c4 = i & 15;
            ((float4*)co_s)[i] =
                ((const float4*)(co + ((size_t)(n0 + j) * BDIM + bb) * CO))[c4];
        }
        __syncthreads();

        #pragma unroll 2
        for (int j = 0; j < TN; ++j) {
            float d = cs[j] - tval;
            float k = fast_exp2(cexp * d * d);
            acc0 += k;
            const float4* crow = ((const float4*)co_s) + j * 16;
            #pragma unroll
            for (int q = 0; q < 16; ++q) {
                float4 w = crow[q];                 // broadcast LDS.128
                accv[q].x = fmaf(k, w.x, accv[q].x);
                accv[q].y = fmaf(k, w.y, accv[q].y);
                accv[q].z = fmaf(k, w.z, accv[q].z);
                accv[q].w = fmaf(k, w.w, accv[q].w);
            }
        }
    }
    __syncthreads();  // done with co_s/cs; re-carve SMEM

    float* v_s = smem;            // 128 rows x 68 (padded)
    float* W_s = smem + 8704;     // 128 rows x 68 (padded)
    float* b_s = smem + 17408;    // 128

    // normalize & stage v (density unnormalized at c=0)
    {
        float inv = 1.0f / (acc0 + 1e-8f);
        float* vr = v_s + tid * 68;
        vr[0] = acc0;
        #pragma unroll
        for (int q = 0; q < 16; ++q) {
            vr[1 + 4 * q + 0] = accv[q].x * inv;
            vr[1 + 4 * q + 1] = accv[q].y * inv;
            vr[1 + 4 * q + 2] = accv[q].z * inv;
            vr[1 + 4 * q + 3] = accv[q].w * inv;
        }
    }
    // stage W (row-padded to 68 for aligned, conflict-free float4 reads) and bias
    for (int i = tid; i < RDIM * 65; i += TM) {
        int r = i / 65;
        int c = i - r * 65;
        W_s[r * 68 + c] = W[i];
    }
    b_s[tid] = bias[tid];
    __syncthreads();

    // projection: thread = output channel r, loop over the block's 128 m rows.
    // Writes are fully coalesced (128 consecutive floats per m).
    const float4* wrow  = (const float4*)(W_s + tid * 68);
    const float   wlast = W_s[tid * 68 + 64];
    const float   bo    = b_s[tid];
    float* outp = out + ((size_t)(blockIdx.x * TM) * BDIM + bb) * RDIM + tid;

    for (int mm = 0; mm < TM; ++mm) {
        const float4* vrow = (const float4*)(v_s + mm * 68);
        float o = bo;
        #pragma unroll
        for (int q = 0; q < 16; ++q) {
            float4 vv = vrow[q];   // broadcast
            float4 ww = wrow[q];   // stride 68 -> conflict-free
            o = fmaf(vv.x, ww.x, o);
            o = fmaf(vv.y, ww.y, o);
            o = fmaf(vv.z, ww.z, o);
            o = fmaf(vv.w, ww.w, o);
        }
        o = fmaf(v_s[mm * 68 + 64], wlast, o);
        outp[(size_t)mm * BDIM * RDIM] = o;
    }
}

extern "C" void kernel_launch(void* const* d_in, const int* in_sizes, int n_in,
                              void* d_out, int out_size)
{
    const float* ci   = (const float*)d_in[0];  // context_in  (N,B,1)
    const float* co   = (const float*)d_in[1];  // context_out (N,B,64)
    const float* ti   = (const float*)d_in[2];  // target_in   (M,B,1)
    const float* ls   = (const float*)d_in[3];  // lengthscale (1,)
    const float* W    = (const float*)d_in[4];  // W (128,65)
    const float* bias = (const float*)d_in[5];  // b (128,)
    float* out = (float*)d_out;

    int N = in_sizes[0] / BDIM;   // 2048
    int M = in_sizes[2] / BDIM;   // 4096

    cudaFuncSetAttribute(convdeepset_kernel,
                         cudaFuncAttributeMaxDynamicSharedMemorySize, SMEM_BYTES);

    dim3 grid(M / TM, BDIM);
    convdeepset_kernel<<<grid, TM, SMEM_BYTES>>>(ci, co, ti, ls, W, bias, out, N, M);
}

// round 2
// speedup vs baseline: 7.1792x; 7.1792x over previous
#include <cuda_runtime.h>
#include <math.h>

#define BDIM 16
#define CO   64
#define RNODES 64          // Chebyshev nodes
#define CC   72            // padded channel count: [0..63]=co, [64]=density, [65..71]=pad
#define RDIM 128
#define NCHUNK_MAX 8

// ---------------- device globals (scratch; no allocation allowed) ----------------
__device__ unsigned g_lo_u, g_hi_u;
__device__ __align__(16) float g_s[RNODES];
__device__ __align__(16) float g_w[RNODES];
__device__ float g_a;
__device__ __align__(16) float g_K[RNODES * RNODES];
__device__ __align__(16) float g_Apart[BDIM * NCHUNK_MAX * RNODES * CC];   // 2.36 MB
__device__ __align__(16) float g_Bt[BDIM * RNODES * CC];                   // 294 KB
__device__ __align__(16) float g_WB[BDIM * RNODES * RDIM];                 // 2.1 MB

// ---------------- helpers ----------------
__device__ __forceinline__ unsigned f2ord(float f) {
    unsigned u = __float_as_uint(f);
    return (u & 0x80000000u) ? ~u : (u | 0x80000000u);
}
__device__ __forceinline__ float ord2f(unsigned u) {
    return (u & 0x80000000u) ? __uint_as_float(u ^ 0x80000000u) : __uint_as_float(~u);
}

// ---------------- kernel 0: init min/max ----------------
__global__ void k_init() {
    g_lo_u = 0xFFFFFFFFu;  // atomicMin target
    g_hi_u = 0u;           // atomicMax target
}

// ---------------- kernel 1: min/max over ci and ti ----------------
__global__ void k_minmax(const float* __restrict__ ci, const float* __restrict__ ti,
                         int nci, int nti) {
    int total = nci + nti;
    float lo = 3.4e38f, hi = -3.4e38f;
    for (int i = blockIdx.x * blockDim.x + threadIdx.x; i < total;
         i += gridDim.x * blockDim.x) {
        float v = (i < nci) ? ci[i] : ti[i - nci];
        lo = fminf(lo, v);
        hi = fmaxf(hi, v);
    }
    #pragma unroll
    for (int o = 16; o; o >>= 1) {
        lo = fminf(lo, __shfl_xor_sync(0xFFFFFFFFu, lo, o));
        hi = fmaxf(hi, __shfl_xor_sync(0xFFFFFFFFu, hi, o));
    }
    if ((threadIdx.x & 31) == 0) {
        atomicMin(&g_lo_u, f2ord(lo));
        atomicMax(&g_hi_u, f2ord(hi));
    }
}

// ---------------- kernel 2: Chebyshev nodes + barycentric weights ----------------
__global__ void k_nodes(const float* __restrict__ ls) {
    int j = threadIdx.x;
    float lo = ord2f(g_lo_u), hi = ord2f(g_hi_u);
    float c = 0.5f * (lo + hi);
    float h = 0.5f * (hi - lo) * 1.0002f + 1e-5f;
    double ang = (double)j * M_PI / (double)(RNODES - 1);
    g_s[j] = c + h * (float)cos(ang);
    float wj = ((j == 0) || (j == RNODES - 1)) ? 0.5f : 1.0f;
    g_w[j] = (j & 1) ? -wj : wj;
    if (j == 0) {
        float l = ls[0];
        g_a = -0.5f / (l * l);
    }
}

// ---------------- kernel 3: node-pair kernel matrix ----------------
__global__ void k_kpq() {
    int p = blockIdx.x, q = threadIdx.x;
    float d = g_s[p] - g_s[q];
    g_K[p * RNODES + q] = expf(g_a * d * d);
}

// ---------------- kernel 4: stage A  A[b,chunk,q,cc] = sum_n L_q(ci_n)*co ----------------
// grid (chunks, B), block 576 = 9 groups x 64 q
#define SA_LT    0                         // Lt[64][129]
#define SA_CO    8256                      // co_s[128][72]
#define SA_INVD  (SA_CO + 128 * CC)        // invd[128]
#define SA_S     (SA_INVD + 128)
#define SA_W     (SA_S + 64)
#define SA_FLOATS (SA_W + 64)

__global__ void __launch_bounds__(576)
k_stageA(const float* __restrict__ ci, const float* __restrict__ co, int b_stride_n) {
    extern __shared__ float sm[];
    float* Lt   = sm + SA_LT;
    float* co_s = sm + SA_CO;
    float* invd = sm + SA_INVD;
    float* s_s  = sm + SA_S;
    float* w_s  = sm + SA_W;

    const int tid = threadIdx.x;
    const int chunk = blockIdx.x, b = blockIdx.y;
    const int n0 = chunk * 256;

    if (tid < 64) { s_s[tid] = g_s[tid]; w_s[tid] = g_w[tid]; }
    __syncthreads();

    const int q = tid & 63, g = tid >> 6;
    float4 acc0 = make_float4(0.f, 0.f, 0.f, 0.f);
    float4 acc1 = make_float4(0.f, 0.f, 0.f, 0.f);

    for (int sub = 0; sub < 2; ++sub) {
        const int nb = n0 + sub * 128;
        __syncthreads();
        if (tid < 128) {
            // barycentric terms for point n = nb + tid
            float x = ci[(nb + tid) * BDIM + b];
            float den = 0.0f;
            #pragma unroll 8
            for (int j = 0; j < 64; ++j) {
                float d = x - s_s[j];
                if (d == 0.0f) d = 1e-30f;
                float r = __fdividef(w_s[j], d);
                den += r;
                Lt[j * 129 + tid] = r;
            }
            invd[tid] = __fdividef(1.0f, den);
        } else {
            // stage co tile: 128 rows x 18 float4 (cols 64..71: density one-hot)
            for (int i = tid - 128; i < 128 * 18; i += 448) {
                int nn = i / 18, c4 = i - nn * 18;
                float4 v;
                if (c4 < 16)
                    v = ((const float4*)(co + ((size_t)(nb + nn) * BDIM + b) * CO))[c4];
                else if (c4 == 16)
                    v = make_float4(1.f, 0.f, 0.f, 0.f);
                else
                    v = make_float4(0.f, 0.f, 0.f, 0.f);
                ((float4*)co_s)[nn * 18 + c4] = v;
            }
        }
        __syncthreads();

        const float4* co4 = (const float4*)co_s;
        #pragma unroll 4
        for (int n = 0; n < 128; ++n) {
            float k = Lt[q * 129 + n] * invd[n];
            float4 x0 = co4[n * 18 + g * 2];
            float4 x1 = co4[n * 18 + g * 2 + 1];
            acc0.x = fmaf(k, x0.x, acc0.x); acc0.y = fmaf(k, x0.y, acc0.y);
            acc0.z = fmaf(k, x0.z, acc0.z); acc0.w = fmaf(k, x0.w, acc0.w);
            acc1.x = fmaf(k, x1.x, acc1.x); acc1.y = fmaf(k, x1.y, acc1.y);
            acc1.z = fmaf(k, x1.z, acc1.z); acc1.w = fmaf(k, x1.w, acc1.w);
        }
    }
    float* ap = g_Apart + (((size_t)b * NCHUNK_MAX + chunk) * RNODES + q) * CC + g * 8;
    ((float4*)ap)[0] = acc0;
    ((float4*)ap)[1] = acc1;
}

// ---------------- kernel 5: stage B  Bt[b,p,cc] = sum_q Kpq * sum_chunk A ----------------
__global__ void __launch_bounds__(576)
k_stageB(int nchunk) {
    __shared__ float Ks[64 * 65];          // transposed [q][p]
    __shared__ float As[RNODES * CC];
    const int tid = threadIdx.x, b = blockIdx.x;

    {   // chunk sum: 4608 elems / 576 threads = 8 each
        int e0 = tid * 8;
        float4 s0 = make_float4(0.f, 0.f, 0.f, 0.f), s1 = s0;
        for (int ch = 0; ch < nchunk; ++ch) {
            const float* ap = g_Apart + ((size_t)b * NCHUNK_MAX + ch) * (RNODES * CC) + e0;
            float4 a0 = ((const float4*)ap)[0], a1 = ((const float4*)ap)[1];
            s0.x += a0.x; s0.y += a0.y; s0.z += a0.z; s0.w += a0.w;
            s1.x += a1.x; s1.y += a1.y; s1.z += a1.z; s1.w += a1.w;
        }
        ((float4*)(As + e0))[0] = s0;
        ((float4*)(As + e0))[1] = s1;
    }
    for (int i = tid; i < 4096; i += 576) {
        int p = i >> 6, q = i & 63;
        Ks[q * 65 + p] = g_K[i];
    }
    __syncthreads();

    const int p = tid & 63, g = tid >> 6;
    float4 acc0 = make_float4(0.f, 0.f, 0.f, 0.f), acc1 = acc0;
    #pragma unroll 4
    for (int qq = 0; qq < 64; ++qq) {
        float kk = Ks[qq * 65 + p];
        float4 a0 = ((const float4*)As)[qq * 18 + g * 2];
        float4 a1 = ((const float4*)As)[qq * 18 + g * 2 + 1];
        acc0.x = fmaf(kk, a0.x, acc0.x); acc0.y = fmaf(kk, a0.y, acc0.y);
        acc0.z = fmaf(kk, a0.z, acc0.z); acc0.w = fmaf(kk, a0.w, acc0.w);
        acc1.x = fmaf(kk, a1.x, acc1.x); acc1.y = fmaf(kk, a1.y, acc1.y);
        acc1.z = fmaf(kk, a1.z, acc1.z); acc1.w = fmaf(kk, a1.w, acc1.w);
    }
    float* bp = g_Bt + ((size_t)b * RNODES + p) * CC + g * 8;
    ((float4*)bp)[0] = acc0;
    ((float4*)bp)[1] = acc1;
}

// ---------------- kernel 6: stage B2  WB[b,p,r] = sum_c W[r,c+1]*Bt[b,p,c] ----------------
#define SB2_BTS 0
#define SB2_WS  (RNODES * CC)              // 4608
#define SB2_FLOATS (SB2_WS + RDIM * 65)    // + 8320

__global__ void __launch_bounds__(512)
k_stageB2(const float* __restrict__ W) {
    extern __shared__ float sm[];
    float* Bts = sm + SB2_BTS;
    float* Ws  = sm + SB2_WS;
    const int tid = threadIdx.x, b = blockIdx.x;

    for (int i = tid; i < RNODES * CC; i += 512) Bts[i] = g_Bt[(size_t)b * RNODES * CC + i];
    for (int i = tid; i < RDIM * 65; i += 512) Ws[i] = W[i];
    __syncthreads();

    const int r = tid & 127, pg = tid >> 7;   // pg 0..3 -> p = pg*16 .. +15
    float acc[16];
    #pragma unroll
    for (int k = 0; k < 16; ++k) acc[k] = 0.0f;
    for (int c = 0; c < 64; ++c) {
        float wv = Ws[r * 65 + (c + 1)];
        #pragma unroll
        for (int k = 0; k < 16; ++k)
            acc[k] = fmaf(wv, Bts[(pg * 16 + k) * CC + c], acc[k]);
    }
    #pragma unroll
    for (int k = 0; k < 16; ++k)
        g_WB[((size_t)b * RNODES + pg * 16 + k) * RDIM + r] = acc[k];
}

// ---------------- kernel 7: stage C  out = (L^T WB)/dens + W0*dens + bias ----------------
#define SC_LAT  0                           // Lat[64][132]
#define SC_WBS  (64 * 132)                  // 8448, 16B aligned
#define SC_DENS (SC_WBS + RNODES * RDIM)    // 16640
#define SC_BTD  (SC_DENS + 128)
#define SC_S    (SC_BTD + 64)
#define SC_W    (SC_S + 64)
#define SC_W0   (SC_W + 64)
#define SC_BIAS (SC_W0 + 128)
#define SC_FLOATS (SC_BIAS + 128)

__global__ void __launch_bounds__(256, 2)
k_stageC(const float* __restrict__ ti, const float* __restrict__ W,
         const float* __restrict__ bias, float* __restrict__ out) {
    extern __shared__ float sm[];
    float* Lat  = sm + SC_LAT;
    float* WBs  = sm + SC_WBS;
    float* dens = sm + SC_DENS;
    float* Btd  = sm + SC_BTD;
    float* s_s  = sm + SC_S;
    float* w_s  = sm + SC_W;
    float* W0s  = sm + SC_W0;
    float* bi_s = sm + SC_BIAS;

    const int tid = threadIdx.x;
    const int m0 = blockIdx.x * 128, b = blockIdx.y;

    for (int i = tid; i < 2048; i += 256)
        ((float4*)WBs)[i] = ((const float4*)(g_WB + (size_t)b * RNODES * RDIM))[i];
    if (tid < 64) {
        Btd[tid] = g_Bt[((size_t)b * RNODES + tid) * CC + 64];
        s_s[tid] = g_s[tid];
        w_s[tid] = g_w[tid];
    }
    if (tid < 128) {
        W0s[tid]  = W[tid * 65];
        bi_s[tid] = bias[tid];
    }
    __syncthreads();

    if (tid < 128) {
        float x = ti[(m0 + tid) * BDIM + b];
        float den = 0.0f;
        #pragma unroll 8
        for (int j = 0; j < 64; ++j) {
            float d = x - s_s[j];
            if (d == 0.0f) d = 1e-30f;
            float r = __fdividef(w_s[j], d);
            den += r;
            Lat[j * 132 + tid] = r;
        }
        float inv = __fdividef(1.0f, den);
        float dm = 0.0f;
        #pragma unroll 8
        for (int j = 0; j < 64; ++j) {
            float v = Lat[j * 132 + tid] * inv;
            Lat[j * 132 + tid] = v;
            dm = fmaf(v, Btd[j], dm);
        }
        dens[tid] = dm;
    }
    __syncthreads();

    const int tx = tid & 15, ty = tid >> 4;
    const int mi = tx * 8, ri = ty * 8;
    float acc[8][8];
    #pragma unroll
    for (int k = 0; k < 8; ++k)
        #pragma unroll
        for (int j = 0; j < 8; ++j) acc[k][j] = 0.0f;

    const float4* Lat4 = (const float4*)Lat;
    const float4* WBs4 = (const float4*)WBs;
    #pragma unroll 4
    for (int p = 0; p < 64; ++p) {
        float4 a0 = Lat4[p * 33 + tx * 2];
        float4 a1 = Lat4[p * 33 + tx * 2 + 1];
        float4 b0 = WBs4[p * 32 + ty * 2];
        float4 b1 = WBs4[p * 32 + ty * 2 + 1];
        float am[8] = {a0.x, a0.y, a0.z, a0.w, a1.x, a1.y, a1.z, a1.w};
        float br[8] = {b0.x, b0.y, b0.z, b0.w, b1.x, b1.y, b1.z, b1.w};
        #pragma unroll
        for (int k = 0; k < 8; ++k)
            #pragma unroll
            for (int j = 0; j < 8; ++j)
                acc[k][j] = fmaf(am[k], br[j], acc[k][j]);
    }

    float w0[8], bi[8];
    #pragma unroll
    for (int j = 0; j < 8; ++j) { w0[j] = W0s[ri + j]; bi[j] = bi_s[ri + j]; }
    #pragma unroll
    for (int k = 0; k < 8; ++k) {
        float dm = dens[mi + k];
        float inv = __fdividef(1.0f, dm + 1e-8f);
        float o[8];
        #pragma unroll
        for (int j = 0; j < 8; ++j)
            o[j] = fmaf(acc[k][j], inv, fmaf(w0[j], dm, bi[j]));
        float* op = out + ((size_t)(m0 + mi + k) * BDIM + b) * RDIM + ri;
        ((float4*)op)[0] = make_float4(o[0], o[1], o[2], o[3]);
        ((float4*)op)[1] = make_float4(o[4], o[5], o[6], o[7]);
    }
}

// ---------------- launch ----------------
extern "C" void kernel_launch(void* const* d_in, const int* in_sizes, int n_in,
                              void* d_out, int out_size)
{
    const float* ci   = (const float*)d_in[0];
    const float* co   = (const float*)d_in[1];
    const float* ti   = (const float*)d_in[2];
    const float* ls   = (const float*)d_in[3];
    const float* W    = (const float*)d_in[4];
    const float* bias = (const float*)d_in[5];
    float* out = (float*)d_out;

    const int N = in_sizes[0] / BDIM;   // 2048
    const int M = in_sizes[2] / BDIM;   // 4096
    const int nchunk = N / 256;         // 8

    static int configured = 0;
    if (!configured) {
        cudaFuncSetAttribute(k_stageA, cudaFuncAttributeMaxDynamicSharedMemorySize,
                             SA_FLOATS * 4);
        cudaFuncSetAttribute(k_stageB2, cudaFuncAttributeMaxDynamicSharedMemorySize,
                             SB2_FLOATS * 4);
        cudaFuncSetAttribute(k_stageC, cudaFuncAttributeMaxDynamicSharedMemorySize,
                             SC_FLOATS * 4);
        configured = 1;
    }

    k_init<<<1, 1>>>();
    k_minmax<<<96, 256>>>(ci, ti, N * BDIM, M * BDIM);
    k_nodes<<<1, RNODES>>>(ls);
    k_kpq<<<RNODES, RNODES>>>();
    k_stageA<<<dim3(nchunk, BDIM), 576, SA_FLOATS * 4>>>(ci, co, N);
    k_stageB<<<BDIM, 576>>>(nchunk);
    k_stageB2<<<BDIM, 512, SB2_FLOATS * 4>>>(W);
    k_stageC<<<dim3(M / 128, BDIM), 256, SC_FLOATS * 4>>>(ti, W, bias, out);
}

// round 3
// speedup vs baseline: 10.4324x; 1.4531x over previous
#include <cuda_runtime.h>
#include <math.h>

#define BDIM 16
#define CO   64
#define RN   32            // Chebyshev nodes
#define CC   72            // padded channels: [0..63]=co, [64]=density, [65..71]=pad
#define RDIM 128
#define NCHUNK 8

// ---------------- device globals (scratch) ----------------
__device__ unsigned g_lo_u, g_hi_u;
__device__ __align__(16) float g_s[RN];
__device__ __align__(16) float g_w[RN];
__device__ float g_a;
__device__ __align__(16) float g_K[RN * RN];
__device__ __align__(16) float g_Apart[BDIM * NCHUNK * RN * CC];   // 1.18 MB
__device__ __align__(16) float g_Btd[BDIM * RN];
__device__ __align__(16) float g_WB[BDIM * RN * RDIM];             // 262 KB

__device__ __forceinline__ unsigned f2ord(float f) {
    unsigned u = __float_as_uint(f);
    return (u & 0x80000000u) ? ~u : (u | 0x80000000u);
}
__device__ __forceinline__ float ord2f(unsigned u) {
    return (u & 0x80000000u) ? __uint_as_float(u ^ 0x80000000u) : __uint_as_float(~u);
}

// ---------------- kernel 1: min/max over ci and ti ----------------
__global__ void k_minmax(const float* __restrict__ ci, const float* __restrict__ ti,
                         int nci, int nti) {
    int total = nci + nti;
    float lo = 3.4e38f, hi = -3.4e38f;
    for (int i = blockIdx.x * blockDim.x + threadIdx.x; i < total;
         i += gridDim.x * blockDim.x) {
        float v = (i < nci) ? ci[i] : ti[i - nci];
        lo = fminf(lo, v);
        hi = fmaxf(hi, v);
    }
    #pragma unroll
    for (int o = 16; o; o >>= 1) {
        lo = fminf(lo, __shfl_xor_sync(0xFFFFFFFFu, lo, o));
        hi = fmaxf(hi, __shfl_xor_sync(0xFFFFFFFFu, hi, o));
    }
    if ((threadIdx.x & 31) == 0) {
        atomicMin(&g_lo_u, f2ord(lo));
        atomicMax(&g_hi_u, f2ord(hi));
    }
}

// ---------------- kernel 2: nodes + weights + node-pair kernel matrix ----------------
__global__ void k_setup(const float* __restrict__ ls) {
    __shared__ float ss[RN];
    int tid = threadIdx.x;
    if (tid == 0) {
        float l = ls[0];
        g_a = -0.5f / (l * l);
    }
    if (tid < RN) {
        float lo = ord2f(g_lo_u), hi = ord2f(g_hi_u);
        float c = 0.5f * (lo + hi);
        float h = 0.5f * (hi - lo) * 1.0002f + 1e-5f;
        double ang = (double)tid * M_PI / (double)(RN - 1);
        float s = c + h * (float)cos(ang);
        g_s[tid] = s;
        ss[tid] = s;
        float wj = ((tid == 0) || (tid == RN - 1)) ? 0.5f : 1.0f;
        g_w[tid] = (tid & 1) ? -wj : wj;
    }
    __syncthreads();
    // 1024 threads = full 32x32 matrix
    int p = tid >> 5, q = tid & 31;
    float d = ss[p] - ss[q];
    g_K[tid] = expf(g_a * d * d);
}

// ---------------- kernel 3: stage A  A[b,chunk,q,cc] = sum_n L_q(ci_n)*co ----------------
// block 288 = 9 groups x 32 q
#define SA_LT    0                          // Lt[32][129]
#define SA_CO    (RN * 129)                 // 4128
#define SA_INVD  (SA_CO + 128 * CC)         // +9216 = 13344
#define SA_S     (SA_INVD + 128)
#define SA_W     (SA_S + RN)
#define SA_FLOATS (SA_W + RN)               // 13536 floats = 54144 B

__global__ void __launch_bounds__(288)
k_stageA(const float* __restrict__ ci, const float* __restrict__ co) {
    extern __shared__ float sm[];
    float* Lt   = sm + SA_LT;
    float* co_s = sm + SA_CO;
    float* invd = sm + SA_INVD;
    float* s_s  = sm + SA_S;
    float* w_s  = sm + SA_W;

    const int tid = threadIdx.x;
    const int chunk = blockIdx.x, b = blockIdx.y;
    const int n0 = chunk * 256;

    if (tid < RN) { s_s[tid] = g_s[tid]; w_s[tid] = g_w[tid]; }
    __syncthreads();

    const int q = tid & 31, g = tid >> 5;   // g 0..8
    float4 acc0 = make_float4(0.f, 0.f, 0.f, 0.f);
    float4 acc1 = make_float4(0.f, 0.f, 0.f, 0.f);

    for (int sub = 0; sub < 2; ++sub) {
        const int nb = n0 + sub * 128;
        __syncthreads();
        if (tid < 128) {
            float x = ci[(nb + tid) * BDIM + b];
            float den = 0.0f;
            #pragma unroll 8
            for (int j = 0; j < RN; ++j) {
                float d = x - s_s[j];
                if (d == 0.0f) d = 1e-30f;
                float r = __fdividef(w_s[j], d);
                den += r;
                Lt[j * 129 + tid] = r;
            }
            invd[tid] = __fdividef(1.0f, den);
        } else {
            for (int i = tid - 128; i < 128 * 18; i += 160) {
                int nn = i / 18, c4 = i - nn * 18;
                float4 v;
                if (c4 < 16)
                    v = ((const float4*)(co + ((size_t)(nb + nn) * BDIM + b) * CO))[c4];
                else if (c4 == 16)
                    v = make_float4(1.f, 0.f, 0.f, 0.f);
                else
                    v = make_float4(0.f, 0.f, 0.f, 0.f);
                ((float4*)co_s)[nn * 18 + c4] = v;
            }
        }
        __syncthreads();

        const float4* co4 = (const float4*)co_s;
        #pragma unroll 4
        for (int n = 0; n < 128; ++n) {
            float k = Lt[q * 129 + n] * invd[n];
            float4 x0 = co4[n * 18 + g * 2];
            float4 x1 = co4[n * 18 + g * 2 + 1];
            acc0.x = fmaf(k, x0.x, acc0.x); acc0.y = fmaf(k, x0.y, acc0.y);
            acc0.z = fmaf(k, x0.z, acc0.z); acc0.w = fmaf(k, x0.w, acc0.w);
            acc1.x = fmaf(k, x1.x, acc1.x); acc1.y = fmaf(k, x1.y, acc1.y);
            acc1.z = fmaf(k, x1.z, acc1.z); acc1.w = fmaf(k, x1.w, acc1.w);
        }
    }
    float* ap = g_Apart + (((size_t)b * NCHUNK + chunk) * RN + q) * CC + g * 8;
    ((float4*)ap)[0] = acc0;
    ((float4*)ap)[1] = acc1;
}

// ---------------- kernel 4: fused stage B  Bt = K * sum_chunk A ; WB = Bt * W^T ----------------
#define SB_AS   0                           // As[32][72] = 2304
#define SB_KS   (RN * CC)                   // 2304
#define SB_BTS  (SB_KS + RN * 33)           // +1056 = 3360
#define SB_WS   (SB_BTS + RN * CC)          // +2304 = 5664
#define SB_FLOATS (SB_WS + RDIM * 65)       // +8320 = 13984 floats = 55936 B

__global__ void __launch_bounds__(256)
k_stageB(const float* __restrict__ W) {
    extern __shared__ float sm[];
    float* As  = sm + SB_AS;
    float* Ks  = sm + SB_KS;
    float* Bts = sm + SB_BTS;
    float* Ws  = sm + SB_WS;
    const int tid = threadIdx.x, b = blockIdx.x;

    {   // chunk-sum partials: 2304 elems / 256 threads = 9 each
        int e0 = tid * 9;
        float s[9];
        #pragma unroll
        for (int k = 0; k < 9; ++k) s[k] = 0.0f;
        for (int ch = 0; ch < NCHUNK; ++ch) {
            const float* ap = g_Apart + ((size_t)b * NCHUNK + ch) * (RN * CC) + e0;
            #pragma unroll
            for (int k = 0; k < 9; ++k) s[k] += ap[k];
        }
        #pragma unroll
        for (int k = 0; k < 9; ++k) As[e0 + k] = s[k];
    }
    for (int i = tid; i < RN * RN; i += 256) {
        int p = i >> 5, q = i & 31;
        Ks[q * 33 + p] = g_K[i];
    }
    for (int i = tid; i < RDIM * 65; i += 256) Ws[i] = W[i];
    __syncthreads();

    {   // Bt[p][cc] = sum_q Kpq * As[q][cc]
        const int p = tid & 31, g = tid >> 5;   // g 0..7, 9 channels each
        const int cb = g * 9;
        float acc[9];
        #pragma unroll
        for (int k = 0; k < 9; ++k) acc[k] = 0.0f;
        #pragma unroll 4
        for (int qq = 0; qq < RN; ++qq) {
            float kk = Ks[qq * 33 + p];
            #pragma unroll
            for (int k = 0; k < 9; ++k)
                acc[k] = fmaf(kk, As[qq * CC + cb + k], acc[k]);
        }
        #pragma unroll
        for (int k = 0; k < 9; ++k) Bts[p * CC + cb + k] = acc[k];
    }
    __syncthreads();
    if (tid < RN) g_Btd[b * RN + tid] = Bts[tid * CC + 64];

    {   // WB[p][r] = sum_c Ws[r][c+1] * Bts[p][c]
        const int r = tid & 127, ph = tid >> 7;  // ph 0..1 -> 16 p each
        float acc[16];
        #pragma unroll
        for (int k = 0; k < 16; ++k) acc[k] = 0.0f;
        for (int c = 0; c < 64; ++c) {
            float wv = Ws[r * 65 + (c + 1)];
            #pragma unroll
            for (int k = 0; k < 16; ++k)
                acc[k] = fmaf(wv, Bts[(ph * 16 + k) * CC + c], acc[k]);
        }
        #pragma unroll
        for (int k = 0; k < 16; ++k)
            g_WB[((size_t)b * RN + ph * 16 + k) * RDIM + r] = acc[k];
    }
}

// ---------------- kernel 5: stage C  out = (L^T WB)/dens + W0*dens + bias ----------------
#define SC_LAT  0                           // Lat[32][132] = 4224
#define SC_WBS  (RN * 132)                  // 4224
#define SC_DENS (SC_WBS + RN * RDIM)        // +4096 = 8320
#define SC_BTD  (SC_DENS + 128)
#define SC_S    (SC_BTD + RN)
#define SC_W    (SC_S + RN)
#define SC_W0   (SC_W + RN)
#define SC_BIAS (SC_W0 + 128)
#define SC_FLOATS (SC_BIAS + 128)           // 8800 floats = 35200 B

__global__ void __launch_bounds__(256, 2)
k_stageC(const float* __restrict__ ti, const float* __restrict__ W,
         const float* __restrict__ bias, float* __restrict__ out) {
    extern __shared__ float sm[];
    float* Lat  = sm + SC_LAT;
    float* WBs  = sm + SC_WBS;
    float* dens = sm + SC_DENS;
    float* Btd  = sm + SC_BTD;
    float* s_s  = sm + SC_S;
    float* w_s  = sm + SC_W;
    float* W0s  = sm + SC_W0;
    float* bi_s = sm + SC_BIAS;

    const int tid = threadIdx.x;
    const int m0 = blockIdx.x * 128, b = blockIdx.y;

    for (int i = tid; i < RN * RDIM / 4; i += 256)
        ((float4*)WBs)[i] = ((const float4*)(g_WB + (size_t)b * RN * RDIM))[i];
    if (tid < RN) {
        Btd[tid] = g_Btd[b * RN + tid];
        s_s[tid] = g_s[tid];
        w_s[tid] = g_w[tid];
    }
    if (tid < 128) {
        W0s[tid]  = W[tid * 65];
        bi_s[tid] = bias[tid];
    }
    __syncthreads();

    if (tid < 128) {
        float x = ti[(m0 + tid) * BDIM + b];
        float den = 0.0f;
        #pragma unroll 8
        for (int j = 0; j < RN; ++j) {
            float d = x - s_s[j];
            if (d == 0.0f) d = 1e-30f;
            float r = __fdividef(w_s[j], d);
            den += r;
            Lat[j * 132 + tid] = r;
        }
        float inv = __fdividef(1.0f, den);
        float dm = 0.0f;
        #pragma unroll 8
        for (int j = 0; j < RN; ++j) {
            float v = Lat[j * 132 + tid] * inv;
            Lat[j * 132 + tid] = v;
            dm = fmaf(v, Btd[j], dm);
        }
        dens[tid] = dm;
    }
    __syncthreads();

    const int tx = tid & 15, ty = tid >> 4;
    const int mi = tx * 8, ri = ty * 8;
    float acc[8][8];
    #pragma unroll
    for (int k = 0; k < 8; ++k)
        #pragma unroll
        for (int j = 0; j < 8; ++j) acc[k][j] = 0.0f;

    const float4* Lat4 = (const float4*)Lat;
    const float4* WBs4 = (const float4*)WBs;
    #pragma unroll 4
    for (int p = 0; p < RN; ++p) {
        float4 a0 = Lat4[p * 33 + tx * 2];
        float4 a1 = Lat4[p * 33 + tx * 2 + 1];
        float4 b0 = WBs4[p * 32 + ty * 2];
        float4 b1 = WBs4[p * 32 + ty * 2 + 1];
        float am[8] = {a0.x, a0.y, a0.z, a0.w, a1.x, a1.y, a1.z, a1.w};
        float br[8] = {b0.x, b0.y, b0.z, b0.w, b1.x, b1.y, b1.z, b1.w};
        #pragma unroll
        for (int k = 0; k < 8; ++k)
            #pragma unroll
            for (int j = 0; j < 8; ++j)
                acc[k][j] = fmaf(am[k], br[j], acc[k][j]);
    }

    float w0[8], bi[8];
    #pragma unroll
    for (int j = 0; j < 8; ++j) { w0[j] = W0s[ri + j]; bi[j] = bi_s[ri + j]; }
    #pragma unroll
    for (int k = 0; k < 8; ++k) {
        float dm = dens[mi + k];
        float inv = __fdividef(1.0f, dm + 1e-8f);
        float o[8];
        #pragma unroll
        for (int j = 0; j < 8; ++j)
            o[j] = fmaf(acc[k][j], inv, fmaf(w0[j], dm, bi[j]));
        float* op = out + ((size_t)(m0 + mi + k) * BDIM + b) * RDIM + ri;
        ((float4*)op)[0] = make_float4(o[0], o[1], o[2], o[3]);
        ((float4*)op)[1] = make_float4(o[4], o[5], o[6], o[7]);
    }
}

// ---------------- launch ----------------
extern "C" void kernel_launch(void* const* d_in, const int* in_sizes, int n_in,
                              void* d_out, int out_size)
{
    const float* ci   = (const float*)d_in[0];
    const float* co   = (const float*)d_in[1];
    const float* ti   = (const float*)d_in[2];
    const float* ls   = (const float*)d_in[3];
    const float* W    = (const float*)d_in[4];
    const float* bias = (const float*)d_in[5];
    float* out = (float*)d_out;

    const int N = in_sizes[0] / BDIM;   // 2048
    const int M = in_sizes[2] / BDIM;   // 4096

    cudaFuncSetAttribute(k_stageA, cudaFuncAttributeMaxDynamicSharedMemorySize,
                         SA_FLOATS * 4);
    cudaFuncSetAttribute(k_stageB, cudaFuncAttributeMaxDynamicSharedMemorySize,
                         SB_FLOATS * 4);
    cudaFuncSetAttribute(k_stageC, cudaFuncAttributeMaxDynamicSharedMemorySize,
                         SC_FLOATS * 4);

    // init min/max atomics via memset nodes (no extra kernel launch)
    void *p_lo, *p_hi;
    cudaGetSymbolAddress(&p_lo, g_lo_u);
    cudaGetSymbolAddress(&p_hi, g_hi_u);
    cudaMemsetAsync(p_lo, 0xFF, 4);
    cudaMemsetAsync(p_hi, 0x00, 4);

    k_minmax<<<96, 256>>>(ci, ti, N * BDIM, M * BDIM);
    k_setup<<<1, 1024>>>(ls);
    k_stageA<<<dim3(N / 256, BDIM), 288, SA_FLOATS * 4>>>(ci, co);
    k_stageB<<<BDIM, 256, SB_FLOATS * 4>>>(W);
    k_stageC<<<dim3(M / 128, BDIM), 256, SC_FLOATS * 4>>>(ti, W, bias, out);
}

// round 4
// speedup vs baseline: 11.0517x; 1.0594x over previous
#include <cuda_runtime.h>
#include <math.h>

#define BDIM 16
#define CO   64
#define RN   32            // Chebyshev nodes
#define CC   72            // padded channels: [0..63]=co, [64]=density, [65..71]=pad
#define RDIM 128

// ---------------- device globals (scratch) ----------------
__device__ unsigned g_lo_u, g_hi_u;
__device__ __align__(16) float g_s[RN];
__device__ __align__(16) float g_w[RN];
__device__ float g_a;
__device__ __align__(16) float g_K[RN * RN];
__device__ __align__(16) float g_A[BDIM * RN * CC];      // 147 KB, atomically accumulated
__device__ __align__(16) float g_Btd[BDIM * RN];
__device__ __align__(16) float g_WB[BDIM * RN * RDIM];   // 262 KB

__device__ __forceinline__ unsigned f2ord(float f) {
    unsigned u = __float_as_uint(f);
    return (u & 0x80000000u) ? ~u : (u | 0x80000000u);
}
__device__ __forceinline__ float ord2f(unsigned u) {
    return (u & 0x80000000u) ? __uint_as_float(u ^ 0x80000000u) : __uint_as_float(~u);
}

// ---------------- kernel 1: min/max over ci and ti ----------------
__global__ void k_minmax(const float* __restrict__ ci, const float* __restrict__ ti,
                         int nci, int nti) {
    int total = nci + nti;
    float lo = 3.4e38f, hi = -3.4e38f;
    for (int i = blockIdx.x * blockDim.x + threadIdx.x; i < total;
         i += gridDim.x * blockDim.x) {
        float v = (i < nci) ? ci[i] : ti[i - nci];
        lo = fminf(lo, v);
        hi = fmaxf(hi, v);
    }
    #pragma unroll
    for (int o = 16; o; o >>= 1) {
        lo = fminf(lo, __shfl_xor_sync(0xFFFFFFFFu, lo, o));
        hi = fmaxf(hi, __shfl_xor_sync(0xFFFFFFFFu, hi, o));
    }
    if ((threadIdx.x & 31) == 0) {
        atomicMin(&g_lo_u, f2ord(lo));
        atomicMax(&g_hi_u, f2ord(hi));
    }
}

// ---------------- kernel 2: nodes + weights + node-pair kernel matrix ----------------
__global__ void k_setup(const float* __restrict__ ls) {
    __shared__ float ss[RN];
    int tid = threadIdx.x;
    if (tid == 0) {
        float l = ls[0];
        g_a = -0.5f / (l * l);
    }
    if (tid < RN) {
        float lo = ord2f(g_lo_u), hi = ord2f(g_hi_u);
        float c = 0.5f * (lo + hi);
        float h = 0.5f * (hi - lo) * 1.0002f + 1e-5f;
        double ang = (double)tid * M_PI / (double)(RN - 1);
        float s = c + h * (float)cos(ang);
        g_s[tid] = s;
        ss[tid] = s;
        float wj = ((tid == 0) || (tid == RN - 1)) ? 0.5f : 1.0f;
        g_w[tid] = (tid & 1) ? -wj : wj;
    }
    __syncthreads();
    int p = tid >> 5, q = tid & 31;
    float d = ss[p] - ss[q];
    g_K[tid] = expf(g_a * d * d);
}

// ---------------- kernel 3: stage A  g_A[b,q,cc] += sum_n L_q(ci_n)*co (atomic) ----------------
// block 288 = 9 groups x 32 q
#define SA_LT    0                          // Lt[32][129]
#define SA_CO    (RN * 129)                 // 4128
#define SA_INVD  (SA_CO + 128 * CC)         // +9216 = 13344
#define SA_S     (SA_INVD + 128)
#define SA_W     (SA_S + RN)
#define SA_FLOATS (SA_W + RN)               // 13536 floats = 54144 B

__global__ void __launch_bounds__(288)
k_stageA(const float* __restrict__ ci, const float* __restrict__ co) {
    extern __shared__ float sm[];
    float* Lt   = sm + SA_LT;
    float* co_s = sm + SA_CO;
    float* invd = sm + SA_INVD;
    float* s_s  = sm + SA_S;
    float* w_s  = sm + SA_W;

    const int tid = threadIdx.x;
    const int chunk = blockIdx.x, b = blockIdx.y;
    const int n0 = chunk * 256;

    if (tid < RN) { s_s[tid] = g_s[tid]; w_s[tid] = g_w[tid]; }
    __syncthreads();

    const int q = tid & 31, g = tid >> 5;   // g 0..8
    float4 acc0 = make_float4(0.f, 0.f, 0.f, 0.f);
    float4 acc1 = make_float4(0.f, 0.f, 0.f, 0.f);

    for (int sub = 0; sub < 2; ++sub) {
        const int nb = n0 + sub * 128;
        __syncthreads();
        if (tid < 128) {
            float x = ci[(nb + tid) * BDIM + b];
            float den = 0.0f;
            #pragma unroll 8
            for (int j = 0; j < RN; ++j) {
                float d = x - s_s[j];
                if (d == 0.0f) d = 1e-30f;
                float r = __fdividef(w_s[j], d);
                den += r;
                Lt[j * 129 + tid] = r;
            }
            invd[tid] = __fdividef(1.0f, den);
        } else {
            for (int i = tid - 128; i < 128 * 18; i += 160) {
                int nn = i / 18, c4 = i - nn * 18;
                float4 v;
                if (c4 < 16)
                    v = ((const float4*)(co + ((size_t)(nb + nn) * BDIM + b) * CO))[c4];
                else if (c4 == 16)
                    v = make_float4(1.f, 0.f, 0.f, 0.f);
                else
                    v = make_float4(0.f, 0.f, 0.f, 0.f);
                ((float4*)co_s)[nn * 18 + c4] = v;
            }
        }
        __syncthreads();

        const float4* co4 = (const float4*)co_s;
        #pragma unroll 4
        for (int n = 0; n < 128; ++n) {
            float k = Lt[q * 129 + n] * invd[n];
            float4 x0 = co4[n * 18 + g * 2];
            float4 x1 = co4[n * 18 + g * 2 + 1];
            acc0.x = fmaf(k, x0.x, acc0.x); acc0.y = fmaf(k, x0.y, acc0.y);
            acc0.z = fmaf(k, x0.z, acc0.z); acc0.w = fmaf(k, x0.w, acc0.w);
            acc1.x = fmaf(k, x1.x, acc1.x); acc1.y = fmaf(k, x1.y, acc1.y);
            acc1.z = fmaf(k, x1.z, acc1.z); acc1.w = fmaf(k, x1.w, acc1.w);
        }
    }
    float* ap = g_A + ((size_t)b * RN + q) * CC + g * 8;
    atomicAdd(ap + 0, acc0.x); atomicAdd(ap + 1, acc0.y);
    atomicAdd(ap + 2, acc0.z); atomicAdd(ap + 3, acc0.w);
    atomicAdd(ap + 4, acc1.x); atomicAdd(ap + 5, acc1.y);
    atomicAdd(ap + 6, acc1.z); atomicAdd(ap + 7, acc1.w);
}

// ---------------- kernel 4: stage B  per (b, 8-p group): Bt = K*A ; WB = Bt*W^T ----------------
#define PB 8                                // p rows per block
#define SB_AS   0                           // As[32][72] = 2304
#define SB_KP   (RN * CC)                   // Kp[8][32] = 256
#define SB_BT   (SB_KP + PB * RN)           // Bt8[8][72] = 576
#define SB_WS   (SB_BT + PB * CC)           // Ws 128*65 = 8320
#define SB_FLOATS (SB_WS + RDIM * 65)       // 11456 floats = 45824 B

__global__ void __launch_bounds__(256)
k_stageB(const float* __restrict__ W) {
    extern __shared__ float sm[];
    float* As  = sm + SB_AS;
    float* Kp  = sm + SB_KP;
    float* Bt8 = sm + SB_BT;
    float* Ws  = sm + SB_WS;
    const int tid = threadIdx.x, b = blockIdx.x, pg = blockIdx.y;
    const int p0 = pg * PB;

    for (int i = tid; i < RN * CC / 4; i += 256)
        ((float4*)As)[i] = ((const float4*)(g_A + (size_t)b * RN * CC))[i];
    if (tid < PB * RN) Kp[tid] = g_K[(p0 + (tid >> 5)) * RN + (tid & 31)];
    for (int i = tid; i < RDIM * 65; i += 256) Ws[i] = W[i];
    __syncthreads();

    // Bt8[pi][c] = sum_q Kp[pi][q] * As[q][c]   (576 outputs)
    for (int i = tid; i < PB * CC; i += 256) {
        int pi = i / CC, c = i - pi * CC;
        float acc = 0.0f;
        #pragma unroll 8
        for (int qq = 0; qq < RN; ++qq)
            acc = fmaf(Kp[pi * RN + qq], As[qq * CC + c], acc);
        Bt8[i] = acc;
        if (c == 64) g_Btd[b * RN + p0 + pi] = acc;
    }
    __syncthreads();

    // WB[p0+pi][r] = sum_c Ws[r][c+1] * Bt8[pi][c]
    const int r = tid & 127, ph = tid >> 7;   // ph 0..1 -> 4 pi each
    float acc[4];
    #pragma unroll
    for (int k = 0; k < 4; ++k) acc[k] = 0.0f;
    #pragma unroll 4
    for (int c = 0; c < 64; ++c) {
        float wv = Ws[r * 65 + (c + 1)];
        #pragma unroll
        for (int k = 0; k < 4; ++k)
            acc[k] = fmaf(wv, Bt8[(ph * 4 + k) * CC + c], acc[k]);
    }
    #pragma unroll
    for (int k = 0; k < 4; ++k)
        g_WB[((size_t)b * RN + p0 + ph * 4 + k) * RDIM + r] = acc[k];
}

// ---------------- kernel 5: stage C  out = (L^T WB)/dens + W0*dens + bias ----------------
#define SC_LAT  0                           // Lat[32][132] = 4224
#define SC_WBS  (RN * 132)
#define SC_DENS (SC_WBS + RN * RDIM)        // +4096 = 8320
#define SC_BTD  (SC_DENS + 128)
#define SC_S    (SC_BTD + RN)
#define SC_W    (SC_S + RN)
#define SC_W0   (SC_W + RN)
#define SC_BIAS (SC_W0 + 128)
#define SC_FLOATS (SC_BIAS + 128)           // 8800 floats = 35200 B

__global__ void __launch_bounds__(256, 2)
k_stageC(const float* __restrict__ ti, const float* __restrict__ W,
         const float* __restrict__ bias, float* __restrict__ out) {
    extern __shared__ float sm[];
    float* Lat  = sm + SC_LAT;
    float* WBs  = sm + SC_WBS;
    float* dens = sm + SC_DENS;
    float* Btd  = sm + SC_BTD;
    float* s_s  = sm + SC_S;
    float* w_s  = sm + SC_W;
    float* W0s  = sm + SC_W0;
    float* bi_s = sm + SC_BIAS;

    const int tid = threadIdx.x;
    const int m0 = blockIdx.x * 128, b = blockIdx.y;

    for (int i = tid; i < RN * RDIM / 4; i += 256)
        ((float4*)WBs)[i] = ((const float4*)(g_WB + (size_t)b * RN * RDIM))[i];
    if (tid < RN) {
        Btd[tid] = g_Btd[b * RN + tid];
        s_s[tid] = g_s[tid];
        w_s[tid] = g_w[tid];
    }
    if (tid < 128) {
        W0s[tid]  = W[tid * 65];
        bi_s[tid] = bias[tid];
    }
    __syncthreads();

    if (tid < 128) {
        float x = ti[(m0 + tid) * BDIM + b];
        float den = 0.0f;
        #pragma unroll 8
        for (int j = 0; j < RN; ++j) {
            float d = x - s_s[j];
            if (d == 0.0f) d = 1e-30f;
            float r = __fdividef(w_s[j], d);
            den += r;
            Lat[j * 132 + tid] = r;
        }
        float inv = __fdividef(1.0f, den);
        float dm = 0.0f;
        #pragma unroll 8
        for (int j = 0; j < RN; ++j) {
            float v = Lat[j * 132 + tid] * inv;
            Lat[j * 132 + tid] = v;
            dm = fmaf(v, Btd[j], dm);
        }
        dens[tid] = dm;
    }
    __syncthreads();

    const int tx = tid & 15, ty = tid >> 4;
    const int mi = tx * 8, ri = ty * 8;
    float acc[8][8];
    #pragma unroll
    for (int k = 0; k < 8; ++k)
        #pragma unroll
        for (int j = 0; j < 8; ++j) acc[k][j] = 0.0f;

    const float4* Lat4 = (const float4*)Lat;
    const float4* WBs4 = (const float4*)WBs;
    #pragma unroll 4
    for (int p = 0; p < RN; ++p) {
        float4 a0 = Lat4[p * 33 + tx * 2];
        float4 a1 = Lat4[p * 33 + tx * 2 + 1];
        float4 b0 = WBs4[p * 32 + ty * 2];
        float4 b1 = WBs4[p * 32 + ty * 2 + 1];
        float am[8] = {a0.x, a0.y, a0.z, a0.w, a1.x, a1.y, a1.z, a1.w};
        float br[8] = {b0.x, b0.y, b0.z, b0.w, b1.x, b1.y, b1.z, b1.w};
        #pragma unroll
        for (int k = 0; k < 8; ++k)
            #pragma unroll
            for (int j = 0; j < 8; ++j)
                acc[k][j] = fmaf(am[k], br[j], acc[k][j]);
    }

    float w0[8], bi[8];
    #pragma unroll
    for (int j = 0; j < 8; ++j) { w0[j] = W0s[ri + j]; bi[j] = bi_s[ri + j]; }
    #pragma unroll
    for (int k = 0; k < 8; ++k) {
        float dm = dens[mi + k];
        float inv = __fdividef(1.0f, dm + 1e-8f);
        float o[8];
        #pragma unroll
        for (int j = 0; j < 8; ++j)
            o[j] = fmaf(acc[k][j], inv, fmaf(w0[j], dm, bi[j]));
        float* op = out + ((size_t)(m0 + mi + k) * BDIM + b) * RDIM + ri;
        ((float4*)op)[0] = make_float4(o[0], o[1], o[2], o[3]);
        ((float4*)op)[1] = make_float4(o[4], o[5], o[6], o[7]);
    }
}

// ---------------- launch ----------------
extern "C" void kernel_launch(void* const* d_in, const int* in_sizes, int n_in,
                              void* d_out, int out_size)
{
    const float* ci   = (const float*)d_in[0];
    const float* co   = (const float*)d_in[1];
    const float* ti   = (const float*)d_in[2];
    const float* ls   = (const float*)d_in[3];
    const float* W    = (const float*)d_in[4];
    const float* bias = (const float*)d_in[5];
    float* out = (float*)d_out;

    const int N = in_sizes[0] / BDIM;   // 2048
    const int M = in_sizes[2] / BDIM;   // 4096

    cudaFuncSetAttribute(k_stageA, cudaFuncAttributeMaxDynamicSharedMemorySize,
                         SA_FLOATS * 4);
    cudaFuncSetAttribute(k_stageB, cudaFuncAttributeMaxDynamicSharedMemorySize,
                         SB_FLOATS * 4);
    cudaFuncSetAttribute(k_stageC, cudaFuncAttributeMaxDynamicSharedMemorySize,
                         SC_FLOATS * 4);

    void *p_lo, *p_hi, *p_A;
    cudaGetSymbolAddress(&p_lo, g_lo_u);
    cudaGetSymbolAddress(&p_hi, g_hi_u);
    cudaGetSymbolAddress(&p_A,  g_A);
    cudaMemsetAsync(p_lo, 0xFF, 4);
    cudaMemsetAsync(p_hi, 0x00, 4);
    cudaMemsetAsync(p_A,  0x00, BDIM * RN * CC * sizeof(float));

    k_minmax<<<96, 256>>>(ci, ti, N * BDIM, M * BDIM);
    k_setup<<<1, 1024>>>(ls);
    k_stageA<<<dim3(N / 256, BDIM), 288, SA_FLOATS * 4>>>(ci, co);
    k_stageB<<<dim3(BDIM, RN / PB), 256, SB_FLOATS * 4>>>(W);
    k_stageC<<<dim3(M / 128, BDIM), 256, SC_FLOATS * 4>>>(ti, W, bias, out);
}